// round 6
// baseline (speedup 1.0000x reference)
#include <cuda_runtime.h>
#include <cuda_bf16.h>
#include <cstdint>

#define SEQ   2048
#define BATCH 2
#define DM    1024
#define NH    16
#define DK    64
#define MROWS (BATCH * SEQ)                   // 4096
#define OUT_ELEMS ((size_t)BATCH * SEQ * DM)  // 4194304

typedef __nv_bfloat16 bf16;

// -------- device scratch (alloc-free rule) --------
__device__ bf16 g_qhi[MROWS * DM], g_qlo[MROWS * DM];
__device__ bf16 g_khi[MROWS * DM], g_klo[MROWS * DM];
__device__ bf16 g_vhi[MROWS * DM], g_vlo[MROWS * DM];
__device__ bf16 g_wqhi[DM * DM],  g_wqlo[DM * DM];
__device__ bf16 g_wvhi[DM * DM],  g_wvlo[DM * DM];
__device__ bf16 g_wohi[DM * DM],  g_wolo[DM * DM];
__device__ bf16 g_Qhi[MROWS * DM], g_Qlo[MROWS * DM];
__device__ bf16 g_Khi[MROWS * DM], g_Klo[MROWS * DM];
__device__ bf16 g_Vthi[MROWS * DM], g_Vtlo[MROWS * DM];  // [b][dm_col][tok]
__device__ bf16 g_Chi[MROWS * DM], g_Clo[MROWS * DM];

__device__ __forceinline__ float neg_inf_f() { return __int_as_float(0xff800000u); }

__device__ __forceinline__ void bsplit(float x, bf16& h, bf16& l)
{
    h = __float2bfloat16(x);
    l = __float2bfloat16(x - __bfloat162float(h));
}

// m16n8k16 BF16 MMA, D += A*B (row.col)
__device__ __forceinline__ void mma_bf16(float4& d,
    uint32_t a0, uint32_t a1, uint32_t a2, uint32_t a3, uint32_t b0, uint32_t b1)
{
    asm volatile(
        "mma.sync.aligned.m16n8k16.row.col.f32.bf16.bf16.f32 "
        "{%0,%1,%2,%3}, {%4,%5,%6,%7}, {%8,%9}, {%0,%1,%2,%3};\n"
        : "+f"(d.x), "+f"(d.y), "+f"(d.z), "+f"(d.w)
        : "r"(a0), "r"(a1), "r"(a2), "r"(a3), "r"(b0), "r"(b1));
}

// online softmax accumulate
__device__ __forceinline__ void upd_ms(float v, float& m, float& s)
{
    if (v > m) { s = s * __expf(m - v) + 1.0f; m = v; }
    else       { s += __expf(v - m); }
}

// ---------------------------------------------------------------------------
// Elementwise split: f32 -> bf16 hi/lo planes.
// ---------------------------------------------------------------------------
__global__ __launch_bounds__(256) void split_kernel(
    const float* __restrict__ x, bf16* __restrict__ hi, bf16* __restrict__ lo, int n4)
{
    int i = blockIdx.x * 256 + threadIdx.x;
    if (i >= n4) return;
    float4 v = ((const float4*)x)[i];
    bf16 h0, l0, h1, l1, h2, l2, h3, l3;
    bsplit(v.x, h0, l0); bsplit(v.y, h1, l1);
    bsplit(v.z, h2, l2); bsplit(v.w, h3, l3);
    ((__nv_bfloat162*)hi)[2 * i]     = __nv_bfloat162(h0, h1);
    ((__nv_bfloat162*)hi)[2 * i + 1] = __nv_bfloat162(h2, h3);
    ((__nv_bfloat162*)lo)[2 * i]     = __nv_bfloat162(l0, l1);
    ((__nv_bfloat162*)lo)[2 * i + 1] = __nv_bfloat162(l2, l3);
}

// ---------------------------------------------------------------------------
// C = A @ W^T + bias, pre-split bf16 hi/lo planes. 3xBF16 MMA.
// mode 0: f32 C. mode 1: Chi/Clo planes. mode 2: transposed V planes.
// ---------------------------------------------------------------------------
__global__ __launch_bounds__(256) void gemm_bf3(
    const bf16* __restrict__ Ahi, const bf16* __restrict__ Alo,
    const bf16* __restrict__ Whi, const bf16* __restrict__ Wlo,
    const float* __restrict__ bias, int M, int N, int K,
    int mode, float* __restrict__ Cf, bf16* __restrict__ Chi, bf16* __restrict__ Clo)
{
    extern __shared__ bf16 smg[];
    bf16* sAhi = smg;                 // 128 x 72
    bf16* sAlo = sAhi + 128 * 72;
    bf16* sBhi = sAlo + 128 * 72;
    bf16* sBlo = sBhi + 128 * 72;

    const int t = threadIdx.x, lane = t & 31, warp = t >> 5;
    const int wm = warp >> 2, wn = warp & 3;
    const int gr = lane >> 2, gc = lane & 3;
    const int rowBase = blockIdx.y * 128, colBase = blockIdx.x * 128;

    float4 acc[4][4] = {};

    for (int k0 = 0; k0 < K; k0 += 64) {
        #pragma unroll
        for (int i = 0; i < 4; i++) {
            int id = t + i * 256;
            int r = id >> 3, c = id & 7;
            *(float4*)&sAhi[r * 72 + c * 8] = *(const float4*)&Ahi[(size_t)(rowBase + r) * K + k0 + c * 8];
            *(float4*)&sAlo[r * 72 + c * 8] = *(const float4*)&Alo[(size_t)(rowBase + r) * K + k0 + c * 8];
            *(float4*)&sBhi[r * 72 + c * 8] = *(const float4*)&Whi[(size_t)(colBase + r) * K + k0 + c * 8];
            *(float4*)&sBlo[r * 72 + c * 8] = *(const float4*)&Wlo[(size_t)(colBase + r) * K + k0 + c * 8];
        }
        __syncthreads();
        #pragma unroll
        for (int ks = 0; ks < 4; ks++) {
            const int kb = ks * 16;
            uint32_t ah[4][4], al[4][4];
            #pragma unroll
            for (int mi = 0; mi < 4; mi++) {
                int m0 = (wm * 64 + mi * 16 + gr) * 72 + kb + 2 * gc;
                ah[mi][0] = *(const uint32_t*)&sAhi[m0];
                ah[mi][1] = *(const uint32_t*)&sAhi[m0 + 8 * 72];
                ah[mi][2] = *(const uint32_t*)&sAhi[m0 + 8];
                ah[mi][3] = *(const uint32_t*)&sAhi[m0 + 8 * 72 + 8];
                al[mi][0] = *(const uint32_t*)&sAlo[m0];
                al[mi][1] = *(const uint32_t*)&sAlo[m0 + 8 * 72];
                al[mi][2] = *(const uint32_t*)&sAlo[m0 + 8];
                al[mi][3] = *(const uint32_t*)&sAlo[m0 + 8 * 72 + 8];
            }
            #pragma unroll
            for (int ni = 0; ni < 4; ni++) {
                int n0 = (wn * 32 + ni * 8 + gr) * 72 + kb + 2 * gc;
                uint32_t bh0 = *(const uint32_t*)&sBhi[n0];
                uint32_t bh1 = *(const uint32_t*)&sBhi[n0 + 8];
                uint32_t bl0 = *(const uint32_t*)&sBlo[n0];
                uint32_t bl1 = *(const uint32_t*)&sBlo[n0 + 8];
                #pragma unroll
                for (int mi = 0; mi < 4; mi++) {
                    mma_bf16(acc[mi][ni], ah[mi][0], ah[mi][1], ah[mi][2], ah[mi][3], bl0, bl1);
                    mma_bf16(acc[mi][ni], al[mi][0], al[mi][1], al[mi][2], al[mi][3], bh0, bh1);
                    mma_bf16(acc[mi][ni], ah[mi][0], ah[mi][1], ah[mi][2], ah[mi][3], bh0, bh1);
                }
            }
        }
        __syncthreads();
    }

    #pragma unroll
    for (int mi = 0; mi < 4; mi++) {
        int r = rowBase + wm * 64 + mi * 16 + gr;
        #pragma unroll
        for (int ni = 0; ni < 4; ni++) {
            int c = colBase + wn * 32 + ni * 8 + 2 * gc;
            float bx = bias[c], by = bias[c + 1];
            float x0 = acc[mi][ni].x + bx, y0 = acc[mi][ni].y + by;
            float z0 = acc[mi][ni].z + bx, w0 = acc[mi][ni].w + by;
            if (mode == 0) {
                *(float2*)&Cf[(size_t)r * N + c]       = make_float2(x0, y0);
                *(float2*)&Cf[(size_t)(r + 8) * N + c] = make_float2(z0, w0);
            } else if (mode == 1) {
                bf16 h0, l0, h1, l1, h2, l2, h3, l3;
                bsplit(x0, h0, l0); bsplit(y0, h1, l1);
                bsplit(z0, h2, l2); bsplit(w0, h3, l3);
                *(__nv_bfloat162*)&Chi[(size_t)r * N + c]       = __nv_bfloat162(h0, h1);
                *(__nv_bfloat162*)&Clo[(size_t)r * N + c]       = __nv_bfloat162(l0, l1);
                *(__nv_bfloat162*)&Chi[(size_t)(r + 8) * N + c] = __nv_bfloat162(h2, h3);
                *(__nv_bfloat162*)&Clo[(size_t)(r + 8) * N + c] = __nv_bfloat162(l2, l3);
            } else {
                int bidx = r >> 11, tok = r & 2047;
                size_t base = ((size_t)bidx * DM + c) * SEQ + tok;
                bf16 h, l;
                bsplit(x0, h, l); Chi[base] = h;            Clo[base] = l;
                bsplit(y0, h, l); Chi[base + SEQ] = h;      Clo[base + SEQ] = l;
                bsplit(z0, h, l); Chi[base + 8] = h;        Clo[base + 8] = l;
                bsplit(w0, h, l); Chi[base + SEQ + 8] = h;  Clo[base + SEQ + 8] = l;
            }
        }
    }
}

// ---------------------------------------------------------------------------
// FUSED attention: scores + softmax + PV for one (qstrip=128, bh).
// Pass 1: QK^T tiles -> raw masked/scaled scores to gmem + online row stats.
// Pass 2: re-read raw (L2-hot), normalize, write attn, PV via 3xBF16 MMA.
// ---------------------------------------------------------------------------
__global__ __launch_bounds__(256, 2) void fused_attn(
    const bf16* __restrict__ Qhi, const bf16* __restrict__ Qlo,
    const bf16* __restrict__ Khi, const bf16* __restrict__ Klo,
    const int* __restrict__ mask, float* __restrict__ attn,
    const bf16* __restrict__ Vthi, const bf16* __restrict__ Vtlo,
    bf16* __restrict__ Chi, bf16* __restrict__ Clo)
{
    extern __shared__ unsigned char smraw[];
    float* sm_m   = (float*)smraw;            // 128
    float* sm_inv = sm_m + 128;               // 128
    float* pm     = sm_inv + 128;             // 4 x 128
    float* ps     = pm + 512;                 // 4 x 128
    int*   smask  = (int*)(ps + 512);         // 2048
    bf16*  dyn    = (bf16*)(smask + 2048);    // union region (73728 B)
    // pass-1 views
    bf16* sQhi = dyn;                 // 128 x 72
    bf16* sQlo = sQhi + 128 * 72;
    bf16* sKhi = sQlo + 128 * 72;
    bf16* sKlo = sKhi + 128 * 72;
    // pass-2 views (alias)
    bf16* sPhi = dyn;                 // 128 x 72
    bf16* sPlo = sPhi + 128 * 72;
    bf16* sVhi = sPlo + 128 * 72;     // 64 x 72
    bf16* sVlo = sVhi + 64 * 72;

    const int t = threadIdx.x, lane = t & 31, warp = t >> 5;
    const int wm = warp >> 2, wn = warp & 3;
    const int gr = lane >> 2, gc = lane & 3;
    const int qBase = blockIdx.x * 128;
    const int bh = blockIdx.y;
    const int b = bh >> 4, h = bh & 15;
    const float scale = 0.125f;

    float* ablk = attn + ((size_t)bh * SEQ + qBase) * SEQ;

    // mask strip + Q strip to smem
    for (int i = t; i < SEQ; i += 256) smask[i] = mask[b * SEQ + i];
    #pragma unroll
    for (int i = 0; i < 4; i++) {
        int id = t + i * 256;
        int r = id >> 3, c8 = (id & 7) * 8;
        size_t off = (size_t)(b * SEQ + qBase + r) * DM + h * DK + c8;
        *(float4*)&sQhi[r * 72 + c8] = *(const float4*)&Qhi[off];
        *(float4*)&sQlo[r * 72 + c8] = *(const float4*)&Qlo[off];
    }
    __syncthreads();

    // ---- pass 1 ----
    float m_t[4][2], s_t[4][2];
    #pragma unroll
    for (int mi = 0; mi < 4; mi++)
        #pragma unroll
        for (int half = 0; half < 2; half++) { m_t[mi][half] = -1e30f; s_t[mi][half] = 0.0f; }

    for (int kt = 0; kt < 16; kt++) {
        const int kBase = kt * 128;
        #pragma unroll
        for (int i = 0; i < 4; i++) {
            int id = t + i * 256;
            int r = id >> 3, c8 = (id & 7) * 8;
            size_t off = (size_t)(b * SEQ + kBase + r) * DM + h * DK + c8;
            *(float4*)&sKhi[r * 72 + c8] = *(const float4*)&Khi[off];
            *(float4*)&sKlo[r * 72 + c8] = *(const float4*)&Klo[off];
        }
        __syncthreads();

        float4 acc[4][4] = {};
        #pragma unroll
        for (int ks = 0; ks < 4; ks++) {
            const int kb = ks * 16;
            uint32_t ah[4][4], al[4][4];
            #pragma unroll
            for (int mi = 0; mi < 4; mi++) {
                int m0 = (wm * 64 + mi * 16 + gr) * 72 + kb + 2 * gc;
                ah[mi][0] = *(const uint32_t*)&sQhi[m0];
                ah[mi][1] = *(const uint32_t*)&sQhi[m0 + 8 * 72];
                ah[mi][2] = *(const uint32_t*)&sQhi[m0 + 8];
                ah[mi][3] = *(const uint32_t*)&sQhi[m0 + 8 * 72 + 8];
                al[mi][0] = *(const uint32_t*)&sQlo[m0];
                al[mi][1] = *(const uint32_t*)&sQlo[m0 + 8 * 72];
                al[mi][2] = *(const uint32_t*)&sQlo[m0 + 8];
                al[mi][3] = *(const uint32_t*)&sQlo[m0 + 8 * 72 + 8];
            }
            #pragma unroll
            for (int ni = 0; ni < 4; ni++) {
                int n0 = (wn * 32 + ni * 8 + gr) * 72 + kb + 2 * gc;
                uint32_t bh0 = *(const uint32_t*)&sKhi[n0];
                uint32_t bh1 = *(const uint32_t*)&sKhi[n0 + 8];
                uint32_t bl0 = *(const uint32_t*)&sKlo[n0];
                uint32_t bl1 = *(const uint32_t*)&sKlo[n0 + 8];
                #pragma unroll
                for (int mi = 0; mi < 4; mi++) {
                    mma_bf16(acc[mi][ni], ah[mi][0], ah[mi][1], ah[mi][2], ah[mi][3], bl0, bl1);
                    mma_bf16(acc[mi][ni], al[mi][0], al[mi][1], al[mi][2], al[mi][3], bh0, bh1);
                    mma_bf16(acc[mi][ni], ah[mi][0], ah[mi][1], ah[mi][2], ah[mi][3], bh0, bh1);
                }
            }
        }

        // scale + mask, write raw, update per-thread row stats
        #pragma unroll
        for (int mi = 0; mi < 4; mi++) {
            int q = wm * 64 + mi * 16 + gr;
            float* row0 = ablk + (size_t)q * SEQ;
            float* row1 = row0 + (size_t)8 * SEQ;
            #pragma unroll
            for (int ni = 0; ni < 4; ni++) {
                int c = kBase + wn * 32 + ni * 8 + 2 * gc;
                int mk0 = smask[c], mk1 = smask[c + 1];
                float vx = mk0 ? acc[mi][ni].x * scale : neg_inf_f();
                float vy = mk1 ? acc[mi][ni].y * scale : neg_inf_f();
                float vz = mk0 ? acc[mi][ni].z * scale : neg_inf_f();
                float vw = mk1 ? acc[mi][ni].w * scale : neg_inf_f();
                *(float2*)&row0[c] = make_float2(vx, vy);
                *(float2*)&row1[c] = make_float2(vz, vw);
                upd_ms(vx, m_t[mi][0], s_t[mi][0]);
                upd_ms(vy, m_t[mi][0], s_t[mi][0]);
                upd_ms(vz, m_t[mi][1], s_t[mi][1]);
                upd_ms(vw, m_t[mi][1], s_t[mi][1]);
            }
        }
        __syncthreads();
    }

    // reduce stats: quad lanes (same rows) -> cross-warp via smem
    #pragma unroll
    for (int o = 1; o <= 2; o <<= 1) {
        #pragma unroll
        for (int mi = 0; mi < 4; mi++)
            #pragma unroll
            for (int half = 0; half < 2; half++) {
                float m2 = __shfl_xor_sync(0xffffffffu, m_t[mi][half], o);
                float s2 = __shfl_xor_sync(0xffffffffu, s_t[mi][half], o);
                float mn = fmaxf(m_t[mi][half], m2);
                s_t[mi][half] = s_t[mi][half] * __expf(m_t[mi][half] - mn) + s2 * __expf(m2 - mn);
                m_t[mi][half] = mn;
            }
    }
    if (gc == 0) {
        #pragma unroll
        for (int mi = 0; mi < 4; mi++)
            #pragma unroll
            for (int half = 0; half < 2; half++) {
                int row = wm * 64 + mi * 16 + gr + half * 8;
                pm[wn * 128 + row] = m_t[mi][half];
                ps[wn * 128 + row] = s_t[mi][half];
            }
    }
    __syncthreads();
    if (wn == 0 && gc == 0) {
        #pragma unroll
        for (int mi = 0; mi < 4; mi++)
            #pragma unroll
            for (int half = 0; half < 2; half++) {
                int row = wm * 64 + mi * 16 + gr + half * 8;
                float M = pm[row], S = ps[row];
                #pragma unroll
                for (int w = 1; w < 4; w++) {
                    float m2 = pm[w * 128 + row], s2 = ps[w * 128 + row];
                    float mn = fmaxf(M, m2);
                    S = S * __expf(M - mn) + s2 * __expf(m2 - mn);
                    M = mn;
                }
                sm_m[row] = M;
                sm_inv[row] = 1.0f / S;
            }
    }
    __syncthreads();

    // ---- pass 2: normalize + write attn + PV (64-token chunks) ----
    const int pr = t >> 1, po = (t & 1) * 32;
    const float mr = sm_m[pr];
    const float ir = sm_inv[pr];

    float4 accp[4][2] = {};

    for (int kc = 0; kc < 32; kc++) {
        // V chunk: 64 d-rows x 64 toks, hi+lo
        #pragma unroll
        for (int i = 0; i < 2; i++) {
            int id = t + i * 256;
            int d = id >> 3, c8 = (id & 7) * 8;
            size_t off = ((size_t)b * DM + h * DK + d) * SEQ + kc * 64 + c8;
            *(float4*)&sVhi[d * 72 + c8] = *(const float4*)&Vthi[off];
            *(float4*)&sVlo[d * 72 + c8] = *(const float4*)&Vtlo[off];
        }
        // normalize this thread's 32 cols of its row, write final, stage split P
        float* prow = ablk + (size_t)pr * SEQ + kc * 64 + po;
        #pragma unroll
        for (int i = 0; i < 8; i++) {
            float4 v = *(const float4*)&prow[i * 4];
            float4 p;
            p.x = __expf(v.x - mr) * ir;
            p.y = __expf(v.y - mr) * ir;
            p.z = __expf(v.z - mr) * ir;
            p.w = __expf(v.w - mr) * ir;
            *(float4*)&prow[i * 4] = p;
            bf16 h0, l0, h1, l1, h2, l2, h3, l3;
            bsplit(p.x, h0, l0); bsplit(p.y, h1, l1);
            bsplit(p.z, h2, l2); bsplit(p.w, h3, l3);
            int widx = pr * 72 + po + i * 4;
            *(__nv_bfloat162*)&sPhi[widx]     = __nv_bfloat162(h0, h1);
            *(__nv_bfloat162*)&sPhi[widx + 2] = __nv_bfloat162(h2, h3);
            *(__nv_bfloat162*)&sPlo[widx]     = __nv_bfloat162(l0, l1);
            *(__nv_bfloat162*)&sPlo[widx + 2] = __nv_bfloat162(l2, l3);
        }
        __syncthreads();

        #pragma unroll
        for (int ks = 0; ks < 4; ks++) {
            const int kb = ks * 16;
            uint32_t ah[4][4], al[4][4];
            #pragma unroll
            for (int mi = 0; mi < 4; mi++) {
                int m0 = (wm * 64 + mi * 16 + gr) * 72 + kb + 2 * gc;
                ah[mi][0] = *(const uint32_t*)&sPhi[m0];
                ah[mi][1] = *(const uint32_t*)&sPhi[m0 + 8 * 72];
                ah[mi][2] = *(const uint32_t*)&sPhi[m0 + 8];
                ah[mi][3] = *(const uint32_t*)&sPhi[m0 + 8 * 72 + 8];
                al[mi][0] = *(const uint32_t*)&sPlo[m0];
                al[mi][1] = *(const uint32_t*)&sPlo[m0 + 8 * 72];
                al[mi][2] = *(const uint32_t*)&sPlo[m0 + 8];
                al[mi][3] = *(const uint32_t*)&sPlo[m0 + 8 * 72 + 8];
            }
            #pragma unroll
            for (int ni = 0; ni < 2; ni++) {
                int n0 = (wn * 16 + ni * 8 + gr) * 72 + kb + 2 * gc;
                uint32_t bh0 = *(const uint32_t*)&sVhi[n0];
                uint32_t bh1 = *(const uint32_t*)&sVhi[n0 + 8];
                uint32_t bl0 = *(const uint32_t*)&sVlo[n0];
                uint32_t bl1 = *(const uint32_t*)&sVlo[n0 + 8];
                #pragma unroll
                for (int mi = 0; mi < 4; mi++) {
                    mma_bf16(accp[mi][ni], ah[mi][0], ah[mi][1], ah[mi][2], ah[mi][3], bl0, bl1);
                    mma_bf16(accp[mi][ni], al[mi][0], al[mi][1], al[mi][2], al[mi][3], bh0, bh1);
                    mma_bf16(accp[mi][ni], ah[mi][0], ah[mi][1], ah[mi][2], ah[mi][3], bh0, bh1);
                }
            }
        }
        __syncthreads();
    }

    // epilogue: Ctx hi/lo planes [token][DM]
    #pragma unroll
    for (int mi = 0; mi < 4; mi++) {
        int q = qBase + wm * 64 + mi * 16 + gr;
        #pragma unroll
        for (int ni = 0; ni < 2; ni++) {
            int d = wn * 16 + ni * 8 + 2 * gc;
            size_t o0 = (size_t)(b * SEQ + q) * DM + h * DK + d;
            size_t o1 = o0 + (size_t)8 * DM;
            bf16 h0, l0, h1, l1;
            bsplit(accp[mi][ni].x, h0, l0); bsplit(accp[mi][ni].y, h1, l1);
            *(__nv_bfloat162*)&Chi[o0] = __nv_bfloat162(h0, h1);
            *(__nv_bfloat162*)&Clo[o0] = __nv_bfloat162(l0, l1);
            bsplit(accp[mi][ni].z, h0, l0); bsplit(accp[mi][ni].w, h1, l1);
            *(__nv_bfloat162*)&Chi[o1] = __nv_bfloat162(h0, h1);
            *(__nv_bfloat162*)&Clo[o1] = __nv_bfloat162(l0, l1);
        }
    }
}

// ---------------------------------------------------------------------------
extern "C" void kernel_launch(void* const* d_in, const int* in_sizes, int n_in,
                              void* d_out, int out_size)
{
    const float* q    = (const float*)d_in[0];
    const float* k    = (const float*)d_in[1];
    const float* v    = (const float*)d_in[2];
    const int*   mask = (const int*)d_in[3];
    const float* w_q  = (const float*)d_in[4];
    const float* b_q  = (const float*)d_in[5];
    const float* w_v  = (const float*)d_in[6];
    const float* b_v  = (const float*)d_in[7];
    const float* w_o  = (const float*)d_in[8];
    const float* b_o  = (const float*)d_in[9];

    float* out  = (float*)d_out;
    float* attn = out + OUT_ELEMS;

    bf16 *qhi, *qlo, *khi, *klo, *vhi, *vlo;
    bf16 *wqhi, *wqlo, *wvhi, *wvlo, *wohi, *wolo;
    bf16 *Qhi, *Qlo, *Khi, *Klo, *Vthi, *Vtlo, *Chi, *Clo;
    cudaGetSymbolAddress((void**)&qhi, g_qhi);   cudaGetSymbolAddress((void**)&qlo, g_qlo);
    cudaGetSymbolAddress((void**)&khi, g_khi);   cudaGetSymbolAddress((void**)&klo, g_klo);
    cudaGetSymbolAddress((void**)&vhi, g_vhi);   cudaGetSymbolAddress((void**)&vlo, g_vlo);
    cudaGetSymbolAddress((void**)&wqhi, g_wqhi); cudaGetSymbolAddress((void**)&wqlo, g_wqlo);
    cudaGetSymbolAddress((void**)&wvhi, g_wvhi); cudaGetSymbolAddress((void**)&wvlo, g_wvlo);
    cudaGetSymbolAddress((void**)&wohi, g_wohi); cudaGetSymbolAddress((void**)&wolo, g_wolo);
    cudaGetSymbolAddress((void**)&Qhi, g_Qhi);   cudaGetSymbolAddress((void**)&Qlo, g_Qlo);
    cudaGetSymbolAddress((void**)&Khi, g_Khi);   cudaGetSymbolAddress((void**)&Klo, g_Klo);
    cudaGetSymbolAddress((void**)&Vthi, g_Vthi); cudaGetSymbolAddress((void**)&Vtlo, g_Vtlo);
    cudaGetSymbolAddress((void**)&Chi, g_Chi);   cudaGetSymbolAddress((void**)&Clo, g_Clo);

    const int gemm_smem  = 4 * 128 * 72 * 2;                       // 73728
    const int fused_smem = (256 + 1024) * 4 + 2048 * 4 + gemm_smem; // 87040

    static bool attr_set = false;
    if (!attr_set) {
        cudaFuncSetAttribute(gemm_bf3, cudaFuncAttributeMaxDynamicSharedMemorySize, gemm_smem);
        cudaFuncSetAttribute(fused_attn, cudaFuncAttributeMaxDynamicSharedMemorySize, fused_smem);
        attr_set = true;
    }

    // 1) split inputs + weights into bf16 hi/lo planes
    split_kernel<<<(MROWS * DM / 4 + 255) / 256, 256>>>(q, qhi, qlo, MROWS * DM / 4);
    split_kernel<<<(MROWS * DM / 4 + 255) / 256, 256>>>(k, khi, klo, MROWS * DM / 4);
    split_kernel<<<(MROWS * DM / 4 + 255) / 256, 256>>>(v, vhi, vlo, MROWS * DM / 4);
    split_kernel<<<(DM * DM / 4 + 255) / 256, 256>>>(w_q, wqhi, wqlo, DM * DM / 4);
    split_kernel<<<(DM * DM / 4 + 255) / 256, 256>>>(w_v, wvhi, wvlo, DM * DM / 4);
    split_kernel<<<(DM * DM / 4 + 255) / 256, 256>>>(w_o, wohi, wolo, DM * DM / 4);

    // 2) projections
    dim3 gProj(DM / 128, MROWS / 128);   // (8, 32)
    gemm_bf3<<<gProj, 256, gemm_smem>>>(qhi, qlo, wqhi, wqlo, b_q, MROWS, DM, DM, 1, nullptr, Qhi, Qlo);
    gemm_bf3<<<gProj, 256, gemm_smem>>>(khi, klo, wqhi, wqlo, b_q, MROWS, DM, DM, 1, nullptr, Khi, Klo);
    gemm_bf3<<<gProj, 256, gemm_smem>>>(vhi, vlo, wvhi, wvlo, b_v, MROWS, DM, DM, 2, nullptr, Vthi, Vtlo);

    // 3) fused scores + softmax + PV
    dim3 gFused(SEQ / 128, BATCH * NH);  // (16, 32)
    fused_attn<<<gFused, 256, fused_smem>>>(Qhi, Qlo, Khi, Klo, mask, attn, Vthi, Vtlo, Chi, Clo);

    // 4) output projection -> f32 out
    gemm_bf3<<<gProj, 256, gemm_smem>>>(Chi, Clo, wohi, wolo, b_o, MROWS, DM, DM, 0, out, nullptr, nullptr);
}

// round 7
// speedup vs baseline: 1.2965x; 1.2965x over previous
#include <cuda_runtime.h>
#include <cuda_bf16.h>
#include <cstdint>

#define SEQ   2048
#define BATCH 2
#define DM    1024
#define NH    16
#define DK    64
#define MROWS (BATCH * SEQ)                   // 4096
#define OUT_ELEMS ((size_t)BATCH * SEQ * DM)  // 4194304
#define NKT   (SEQ / 128)                     // 16 ktiles per row

typedef __nv_bfloat16 bf16;

// -------- device scratch (alloc-free rule) --------
__device__ bf16 g_qhi[MROWS * DM], g_qlo[MROWS * DM];
__device__ bf16 g_khi[MROWS * DM], g_klo[MROWS * DM];
__device__ bf16 g_vhi[MROWS * DM], g_vlo[MROWS * DM];
__device__ bf16 g_wqhi[DM * DM],  g_wqlo[DM * DM];
__device__ bf16 g_wvhi[DM * DM],  g_wvlo[DM * DM];
__device__ bf16 g_wohi[DM * DM],  g_wolo[DM * DM];
__device__ bf16 g_Qhi[MROWS * DM], g_Qlo[MROWS * DM];
__device__ bf16 g_Khi[MROWS * DM], g_Klo[MROWS * DM];
__device__ bf16 g_Vthi[MROWS * DM], g_Vtlo[MROWS * DM];  // [b][dm_col][tok]
__device__ bf16 g_Chi[MROWS * DM], g_Clo[MROWS * DM];
// per-(bh, q, ktile) partial softmax stats
__device__ float g_pm[BATCH * NH * SEQ * NKT];
__device__ float g_ps[BATCH * NH * SEQ * NKT];

__device__ __forceinline__ float neg_inf_f() { return __int_as_float(0xff800000u); }

__device__ __forceinline__ void bsplit(float x, bf16& h, bf16& l)
{
    h = __float2bfloat16(x);
    l = __float2bfloat16(x - __bfloat162float(h));
}

// m16n8k16 BF16 MMA, D += A*B (row.col)
__device__ __forceinline__ void mma_bf16(float4& d,
    uint32_t a0, uint32_t a1, uint32_t a2, uint32_t a3, uint32_t b0, uint32_t b1)
{
    asm volatile(
        "mma.sync.aligned.m16n8k16.row.col.f32.bf16.bf16.f32 "
        "{%0,%1,%2,%3}, {%4,%5,%6,%7}, {%8,%9}, {%0,%1,%2,%3};\n"
        : "+f"(d.x), "+f"(d.y), "+f"(d.z), "+f"(d.w)
        : "r"(a0), "r"(a1), "r"(a2), "r"(a3), "r"(b0), "r"(b1));
}

__device__ __forceinline__ void upd_ms(float v, float& m, float& s)
{
    if (v > m) { s = s * __expf(m - v) + 1.0f; m = v; }
    else       { s += __expf(v - m); }
}

// ---------------------------------------------------------------------------
__global__ __launch_bounds__(256) void split_kernel(
    const float* __restrict__ x, bf16* __restrict__ hi, bf16* __restrict__ lo, int n4)
{
    int i = blockIdx.x * 256 + threadIdx.x;
    if (i >= n4) return;
    float4 v = ((const float4*)x)[i];
    bf16 h0, l0, h1, l1, h2, l2, h3, l3;
    bsplit(v.x, h0, l0); bsplit(v.y, h1, l1);
    bsplit(v.z, h2, l2); bsplit(v.w, h3, l3);
    ((__nv_bfloat162*)hi)[2 * i]     = __nv_bfloat162(h0, h1);
    ((__nv_bfloat162*)hi)[2 * i + 1] = __nv_bfloat162(h2, h3);
    ((__nv_bfloat162*)lo)[2 * i]     = __nv_bfloat162(l0, l1);
    ((__nv_bfloat162*)lo)[2 * i + 1] = __nv_bfloat162(l2, l3);
}

// ---------------------------------------------------------------------------
// C = A @ W^T + bias, pre-split bf16 hi/lo planes. 3xBF16 MMA.
// mode 0: f32 C. mode 1: Chi/Clo planes. mode 2: transposed V planes.
// ---------------------------------------------------------------------------
__global__ __launch_bounds__(256) void gemm_bf3(
    const bf16* __restrict__ Ahi, const bf16* __restrict__ Alo,
    const bf16* __restrict__ Whi, const bf16* __restrict__ Wlo,
    const float* __restrict__ bias, int M, int N, int K,
    int mode, float* __restrict__ Cf, bf16* __restrict__ Chi, bf16* __restrict__ Clo)
{
    extern __shared__ bf16 smg[];
    bf16* sAhi = smg;                 // 128 x 72
    bf16* sAlo = sAhi + 128 * 72;
    bf16* sBhi = sAlo + 128 * 72;
    bf16* sBlo = sBhi + 128 * 72;

    const int t = threadIdx.x, lane = t & 31, warp = t >> 5;
    const int wm = warp >> 2, wn = warp & 3;
    const int gr = lane >> 2, gc = lane & 3;
    const int rowBase = blockIdx.y * 128, colBase = blockIdx.x * 128;

    float4 acc[4][4] = {};

    for (int k0 = 0; k0 < K; k0 += 64) {
        #pragma unroll
        for (int i = 0; i < 4; i++) {
            int id = t + i * 256;
            int r = id >> 3, c = id & 7;
            *(float4*)&sAhi[r * 72 + c * 8] = *(const float4*)&Ahi[(size_t)(rowBase + r) * K + k0 + c * 8];
            *(float4*)&sAlo[r * 72 + c * 8] = *(const float4*)&Alo[(size_t)(rowBase + r) * K + k0 + c * 8];
            *(float4*)&sBhi[r * 72 + c * 8] = *(const float4*)&Whi[(size_t)(colBase + r) * K + k0 + c * 8];
            *(float4*)&sBlo[r * 72 + c * 8] = *(const float4*)&Wlo[(size_t)(colBase + r) * K + k0 + c * 8];
        }
        __syncthreads();
        #pragma unroll
        for (int ks = 0; ks < 4; ks++) {
            const int kb = ks * 16;
            uint32_t ah[4][4], al[4][4];
            #pragma unroll
            for (int mi = 0; mi < 4; mi++) {
                int m0 = (wm * 64 + mi * 16 + gr) * 72 + kb + 2 * gc;
                ah[mi][0] = *(const uint32_t*)&sAhi[m0];
                ah[mi][1] = *(const uint32_t*)&sAhi[m0 + 8 * 72];
                ah[mi][2] = *(const uint32_t*)&sAhi[m0 + 8];
                ah[mi][3] = *(const uint32_t*)&sAhi[m0 + 8 * 72 + 8];
                al[mi][0] = *(const uint32_t*)&sAlo[m0];
                al[mi][1] = *(const uint32_t*)&sAlo[m0 + 8 * 72];
                al[mi][2] = *(const uint32_t*)&sAlo[m0 + 8];
                al[mi][3] = *(const uint32_t*)&sAlo[m0 + 8 * 72 + 8];
            }
            #pragma unroll
            for (int ni = 0; ni < 4; ni++) {
                int n0 = (wn * 32 + ni * 8 + gr) * 72 + kb + 2 * gc;
                uint32_t bh0 = *(const uint32_t*)&sBhi[n0];
                uint32_t bh1 = *(const uint32_t*)&sBhi[n0 + 8];
                uint32_t bl0 = *(const uint32_t*)&sBlo[n0];
                uint32_t bl1 = *(const uint32_t*)&sBlo[n0 + 8];
                #pragma unroll
                for (int mi = 0; mi < 4; mi++) {
                    mma_bf16(acc[mi][ni], ah[mi][0], ah[mi][1], ah[mi][2], ah[mi][3], bl0, bl1);
                    mma_bf16(acc[mi][ni], al[mi][0], al[mi][1], al[mi][2], al[mi][3], bh0, bh1);
                    mma_bf16(acc[mi][ni], ah[mi][0], ah[mi][1], ah[mi][2], ah[mi][3], bh0, bh1);
                }
            }
        }
        __syncthreads();
    }

    #pragma unroll
    for (int mi = 0; mi < 4; mi++) {
        int r = rowBase + wm * 64 + mi * 16 + gr;
        #pragma unroll
        for (int ni = 0; ni < 4; ni++) {
            int c = colBase + wn * 32 + ni * 8 + 2 * gc;
            float bx = bias[c], by = bias[c + 1];
            float x0 = acc[mi][ni].x + bx, y0 = acc[mi][ni].y + by;
            float z0 = acc[mi][ni].z + bx, w0 = acc[mi][ni].w + by;
            if (mode == 0) {
                *(float2*)&Cf[(size_t)r * N + c]       = make_float2(x0, y0);
                *(float2*)&Cf[(size_t)(r + 8) * N + c] = make_float2(z0, w0);
            } else if (mode == 1) {
                bf16 h0, l0, h1, l1, h2, l2, h3, l3;
                bsplit(x0, h0, l0); bsplit(y0, h1, l1);
                bsplit(z0, h2, l2); bsplit(w0, h3, l3);
                *(__nv_bfloat162*)&Chi[(size_t)r * N + c]       = __nv_bfloat162(h0, h1);
                *(__nv_bfloat162*)&Clo[(size_t)r * N + c]       = __nv_bfloat162(l0, l1);
                *(__nv_bfloat162*)&Chi[(size_t)(r + 8) * N + c] = __nv_bfloat162(h2, h3);
                *(__nv_bfloat162*)&Clo[(size_t)(r + 8) * N + c] = __nv_bfloat162(l2, l3);
            } else {
                int bidx = r >> 11, tok = r & 2047;
                size_t base = ((size_t)bidx * DM + c) * SEQ + tok;
                bf16 h, l;
                bsplit(x0, h, l); Chi[base] = h;            Clo[base] = l;
                bsplit(y0, h, l); Chi[base + SEQ] = h;      Clo[base + SEQ] = l;
                bsplit(z0, h, l); Chi[base + 8] = h;        Clo[base + 8] = l;
                bsplit(w0, h, l); Chi[base + SEQ + 8] = h;  Clo[base + SEQ + 8] = l;
            }
        }
    }
}

// ---------------------------------------------------------------------------
// Scores + per-ktile partial softmax stats.
// attn[b,h,q,k] = (Qh.Kh)*0.125 or -inf; also writes (m,s) partial for this
// 128-col ktile per row into g_pm/g_ps.
// ---------------------------------------------------------------------------
__global__ __launch_bounds__(256) void attn_scores_bf(
    const bf16* __restrict__ Qhi, const bf16* __restrict__ Qlo,
    const bf16* __restrict__ Khi, const bf16* __restrict__ Klo,
    const int* __restrict__ mask, float* __restrict__ attn,
    float* __restrict__ pm_out, float* __restrict__ ps_out)
{
    extern __shared__ bf16 sms[];
    bf16* sQhi = sms;                // 128 x 72
    bf16* sQlo = sQhi + 128 * 72;
    bf16* sKhi = sQlo + 128 * 72;
    bf16* sKlo = sKhi + 128 * 72;
    __shared__ float pm[4 * 128], ps[4 * 128];

    const int t = threadIdx.x, lane = t & 31, warp = t >> 5;
    const int wm = warp >> 2, wn = warp & 3;
    const int gr = lane >> 2, gc = lane & 3;
    const int bh = blockIdx.z;
    const int b = bh >> 4, h = bh & 15;
    const int qBase = blockIdx.y * 128;
    const int kBase = blockIdx.x * 128;
    const int kt = blockIdx.x;

    #pragma unroll
    for (int i = 0; i < 4; i++) {
        int id = t + i * 256;
        int r = id >> 3, c = id & 7;
        size_t qoff = (size_t)(b * SEQ + qBase + r) * DM + h * DK + c * 8;
        size_t koff = (size_t)(b * SEQ + kBase + r) * DM + h * DK + c * 8;
        *(float4*)&sQhi[r * 72 + c * 8] = *(const float4*)&Qhi[qoff];
        *(float4*)&sQlo[r * 72 + c * 8] = *(const float4*)&Qlo[qoff];
        *(float4*)&sKhi[r * 72 + c * 8] = *(const float4*)&Khi[koff];
        *(float4*)&sKlo[r * 72 + c * 8] = *(const float4*)&Klo[koff];
    }
    __syncthreads();

    float4 acc[4][4] = {};
    #pragma unroll
    for (int ks = 0; ks < 4; ks++) {
        const int kb = ks * 16;
        uint32_t ah[4][4], al[4][4];
        #pragma unroll
        for (int mi = 0; mi < 4; mi++) {
            int m0 = (wm * 64 + mi * 16 + gr) * 72 + kb + 2 * gc;
            ah[mi][0] = *(const uint32_t*)&sQhi[m0];
            ah[mi][1] = *(const uint32_t*)&sQhi[m0 + 8 * 72];
            ah[mi][2] = *(const uint32_t*)&sQhi[m0 + 8];
            ah[mi][3] = *(const uint32_t*)&sQhi[m0 + 8 * 72 + 8];
            al[mi][0] = *(const uint32_t*)&sQlo[m0];
            al[mi][1] = *(const uint32_t*)&sQlo[m0 + 8 * 72];
            al[mi][2] = *(const uint32_t*)&sQlo[m0 + 8];
            al[mi][3] = *(const uint32_t*)&sQlo[m0 + 8 * 72 + 8];
        }
        #pragma unroll
        for (int ni = 0; ni < 4; ni++) {
            int n0 = (wn * 32 + ni * 8 + gr) * 72 + kb + 2 * gc;
            uint32_t bh0 = *(const uint32_t*)&sKhi[n0];
            uint32_t bh1 = *(const uint32_t*)&sKhi[n0 + 8];
            uint32_t bl0 = *(const uint32_t*)&sKlo[n0];
            uint32_t bl1 = *(const uint32_t*)&sKlo[n0 + 8];
            #pragma unroll
            for (int mi = 0; mi < 4; mi++) {
                mma_bf16(acc[mi][ni], ah[mi][0], ah[mi][1], ah[mi][2], ah[mi][3], bl0, bl1);
                mma_bf16(acc[mi][ni], al[mi][0], al[mi][1], al[mi][2], al[mi][3], bh0, bh1);
                mma_bf16(acc[mi][ni], ah[mi][0], ah[mi][1], ah[mi][2], ah[mi][3], bh0, bh1);
            }
        }
    }

    const float scale = 0.125f;
    float m_t[4][2], s_t[4][2];
    #pragma unroll
    for (int mi = 0; mi < 4; mi++)
        #pragma unroll
        for (int hf = 0; hf < 2; hf++) { m_t[mi][hf] = -1e30f; s_t[mi][hf] = 0.0f; }

    #pragma unroll
    for (int mi = 0; mi < 4; mi++) {
        int q = qBase + wm * 64 + mi * 16 + gr;
        size_t row0 = ((size_t)bh * SEQ + q) * SEQ;
        size_t row1 = row0 + (size_t)8 * SEQ;
        #pragma unroll
        for (int ni = 0; ni < 4; ni++) {
            int c = kBase + wn * 32 + ni * 8 + 2 * gc;
            int mk0 = mask[b * SEQ + c], mk1 = mask[b * SEQ + c + 1];
            float vx = mk0 ? acc[mi][ni].x * scale : neg_inf_f();
            float vy = mk1 ? acc[mi][ni].y * scale : neg_inf_f();
            float vz = mk0 ? acc[mi][ni].z * scale : neg_inf_f();
            float vw = mk1 ? acc[mi][ni].w * scale : neg_inf_f();
            *(float2*)&attn[row0 + c] = make_float2(vx, vy);
            *(float2*)&attn[row1 + c] = make_float2(vz, vw);
            upd_ms(vx, m_t[mi][0], s_t[mi][0]);
            upd_ms(vy, m_t[mi][0], s_t[mi][0]);
            upd_ms(vz, m_t[mi][1], s_t[mi][1]);
            upd_ms(vw, m_t[mi][1], s_t[mi][1]);
        }
    }

    // reduce over gc quad (lane bits 0-1), then cross-warp (wn) via smem
    #pragma unroll
    for (int o = 1; o <= 2; o <<= 1) {
        #pragma unroll
        for (int mi = 0; mi < 4; mi++)
            #pragma unroll
            for (int hf = 0; hf < 2; hf++) {
                float m2 = __shfl_xor_sync(0xffffffffu, m_t[mi][hf], o);
                float s2 = __shfl_xor_sync(0xffffffffu, s_t[mi][hf], o);
                float mn = fmaxf(m_t[mi][hf], m2);
                s_t[mi][hf] = s_t[mi][hf] * __expf(m_t[mi][hf] - mn) + s2 * __expf(m2 - mn);
                m_t[mi][hf] = mn;
            }
    }
    if (gc == 0) {
        #pragma unroll
        for (int mi = 0; mi < 4; mi++)
            #pragma unroll
            for (int hf = 0; hf < 2; hf++) {
                int row = wm * 64 + mi * 16 + gr + hf * 8;
                pm[wn * 128 + row] = m_t[mi][hf];
                ps[wn * 128 + row] = s_t[mi][hf];
            }
    }
    __syncthreads();
    if (t < 128) {
        int row = t;
        float M = pm[row], S = ps[row];
        #pragma unroll
        for (int w = 1; w < 4; w++) {
            float m2 = pm[w * 128 + row], s2 = ps[w * 128 + row];
            float mn = fmaxf(M, m2);
            S = S * __expf(M - mn) + s2 * __expf(m2 - mn);
            M = mn;
        }
        size_t sidx = ((size_t)bh * SEQ + qBase + row) * NKT + kt;
        pm_out[sidx] = M;
        ps_out[sidx] = S;
    }
}

// ---------------------------------------------------------------------------
// Softmax (stats from partials) + PV. Block = (qtile 128, bh).
// ---------------------------------------------------------------------------
__global__ __launch_bounds__(256) void softmax_pv_bf(
    float* __restrict__ attn,
    const float* __restrict__ pm_in, const float* __restrict__ ps_in,
    const bf16* __restrict__ Vthi, const bf16* __restrict__ Vtlo,
    bf16* __restrict__ Chi, bf16* __restrict__ Clo)
{
    extern __shared__ unsigned char smraw[];
    float* sm_m   = (float*)smraw;            // 128
    float* sm_inv = sm_m + 128;               // 128
    bf16* sPhi = (bf16*)(sm_inv + 128);       // 128 x 136
    bf16* sPlo = sPhi + 128 * 136;
    bf16* sVhi = sPlo + 128 * 136;            // 64 x 136
    bf16* sVlo = sVhi + 64 * 136;

    const int t = threadIdx.x, lane = t & 31, warp = t >> 5;
    const int gr = lane >> 2, gc = lane & 3;
    const int wm = warp >> 2, wn = warp & 3;
    const int qBase = blockIdx.x * 128;
    const int bh = blockIdx.y;
    const int b = bh >> 4, h = bh & 15;

    float* ablk = attn + ((size_t)bh * SEQ + qBase) * SEQ;

    // ---- stats from partials ----
    if (t < 128) {
        size_t base = ((size_t)bh * SEQ + qBase + t) * NKT;
        float M = pm_in[base], S = ps_in[base];
        #pragma unroll
        for (int i = 1; i < NKT; i++) {
            float m2 = pm_in[base + i], s2 = ps_in[base + i];
            float mn = fmaxf(M, m2);
            S = S * __expf(M - mn) + s2 * __expf(m2 - mn);
            M = mn;
        }
        sm_m[t] = M;
        sm_inv[t] = 1.0f / S;
    }
    __syncthreads();

    // ---- normalize + PV ----
    const int pr = t >> 1, ho = (t & 1) * 64;
    const float mr = sm_m[pr];
    const float ir = sm_inv[pr];

    float4 acc[4][2] = {};

    for (int kt = 0; kt < 16; kt++) {
        #pragma unroll
        for (int i = 0; i < 4; i++) {
            int id = t + i * 256;
            int d = id >> 4, c = id & 15;
            size_t off = ((size_t)b * DM + h * DK + d) * SEQ + kt * 128 + c * 8;
            *(float4*)&sVhi[d * 136 + c * 8] = *(const float4*)&Vthi[off];
            *(float4*)&sVlo[d * 136 + c * 8] = *(const float4*)&Vtlo[off];
        }
        float* prow = ablk + (size_t)pr * SEQ + kt * 128 + ho;
        #pragma unroll
        for (int i = 0; i < 16; i++) {
            float4 v = *(const float4*)&prow[i * 4];
            float4 p;
            p.x = __expf(v.x - mr) * ir;
            p.y = __expf(v.y - mr) * ir;
            p.z = __expf(v.z - mr) * ir;
            p.w = __expf(v.w - mr) * ir;
            *(float4*)&prow[i * 4] = p;
            bf16 h0, l0, h1, l1, h2, l2, h3, l3;
            bsplit(p.x, h0, l0); bsplit(p.y, h1, l1);
            bsplit(p.z, h2, l2); bsplit(p.w, h3, l3);
            int widx = pr * 136 + ho + i * 4;
            *(__nv_bfloat162*)&sPhi[widx]     = __nv_bfloat162(h0, h1);
            *(__nv_bfloat162*)&sPhi[widx + 2] = __nv_bfloat162(h2, h3);
            *(__nv_bfloat162*)&sPlo[widx]     = __nv_bfloat162(l0, l1);
            *(__nv_bfloat162*)&sPlo[widx + 2] = __nv_bfloat162(l2, l3);
        }
        __syncthreads();
        #pragma unroll
        for (int ks = 0; ks < 8; ks++) {
            const int kb = ks * 16;
            uint32_t ah[4][4], al[4][4];
            #pragma unroll
            for (int mi = 0; mi < 4; mi++) {
                int m0 = (wm * 64 + mi * 16 + gr) * 136 + kb + 2 * gc;
                ah[mi][0] = *(const uint32_t*)&sPhi[m0];
                ah[mi][1] = *(const uint32_t*)&sPhi[m0 + 8 * 136];
                ah[mi][2] = *(const uint32_t*)&sPhi[m0 + 8];
                ah[mi][3] = *(const uint32_t*)&sPhi[m0 + 8 * 136 + 8];
                al[mi][0] = *(const uint32_t*)&sPlo[m0];
                al[mi][1] = *(const uint32_t*)&sPlo[m0 + 8 * 136];
                al[mi][2] = *(const uint32_t*)&sPlo[m0 + 8];
                al[mi][3] = *(const uint32_t*)&sPlo[m0 + 8 * 136 + 8];
            }
            #pragma unroll
            for (int ni = 0; ni < 2; ni++) {
                int n0 = (wn * 16 + ni * 8 + gr) * 136 + kb + 2 * gc;
                uint32_t bh0 = *(const uint32_t*)&sVhi[n0];
                uint32_t bh1 = *(const uint32_t*)&sVhi[n0 + 8];
                uint32_t bl0 = *(const uint32_t*)&sVlo[n0];
                uint32_t bl1 = *(const uint32_t*)&sVlo[n0 + 8];
                #pragma unroll
                for (int mi = 0; mi < 4; mi++) {
                    mma_bf16(acc[mi][ni], ah[mi][0], ah[mi][1], ah[mi][2], ah[mi][3], bl0, bl1);
                    mma_bf16(acc[mi][ni], al[mi][0], al[mi][1], al[mi][2], al[mi][3], bh0, bh1);
                    mma_bf16(acc[mi][ni], ah[mi][0], ah[mi][1], ah[mi][2], ah[mi][3], bh0, bh1);
                }
            }
        }
        __syncthreads();
    }

    #pragma unroll
    for (int mi = 0; mi < 4; mi++) {
        int q = qBase + wm * 64 + mi * 16 + gr;
        #pragma unroll
        for (int ni = 0; ni < 2; ni++) {
            int d = wn * 16 + ni * 8 + 2 * gc;
            size_t o0 = (size_t)(b * SEQ + q) * DM + h * DK + d;
            size_t o1 = o0 + (size_t)8 * DM;
            bf16 h0, l0, h1, l1;
            bsplit(acc[mi][ni].x, h0, l0); bsplit(acc[mi][ni].y, h1, l1);
            *(__nv_bfloat162*)&Chi[o0] = __nv_bfloat162(h0, h1);
            *(__nv_bfloat162*)&Clo[o0] = __nv_bfloat162(l0, l1);
            bsplit(acc[mi][ni].z, h0, l0); bsplit(acc[mi][ni].w, h1, l1);
            *(__nv_bfloat162*)&Chi[o1] = __nv_bfloat162(h0, h1);
            *(__nv_bfloat162*)&Clo[o1] = __nv_bfloat162(l0, l1);
        }
    }
}

// ---------------------------------------------------------------------------
extern "C" void kernel_launch(void* const* d_in, const int* in_sizes, int n_in,
                              void* d_out, int out_size)
{
    const float* q    = (const float*)d_in[0];
    const float* k    = (const float*)d_in[1];
    const float* v    = (const float*)d_in[2];
    const int*   mask = (const int*)d_in[3];
    const float* w_q  = (const float*)d_in[4];
    const float* b_q  = (const float*)d_in[5];
    const float* w_v  = (const float*)d_in[6];
    const float* b_v  = (const float*)d_in[7];
    const float* w_o  = (const float*)d_in[8];
    const float* b_o  = (const float*)d_in[9];

    float* out  = (float*)d_out;
    float* attn = out + OUT_ELEMS;

    bf16 *qhi, *qlo, *khi, *klo, *vhi, *vlo;
    bf16 *wqhi, *wqlo, *wvhi, *wvlo, *wohi, *wolo;
    bf16 *Qhi, *Qlo, *Khi, *Klo, *Vthi, *Vtlo, *Chi, *Clo;
    float *pmb, *psb;
    cudaGetSymbolAddress((void**)&qhi, g_qhi);   cudaGetSymbolAddress((void**)&qlo, g_qlo);
    cudaGetSymbolAddress((void**)&khi, g_khi);   cudaGetSymbolAddress((void**)&klo, g_klo);
    cudaGetSymbolAddress((void**)&vhi, g_vhi);   cudaGetSymbolAddress((void**)&vlo, g_vlo);
    cudaGetSymbolAddress((void**)&wqhi, g_wqhi); cudaGetSymbolAddress((void**)&wqlo, g_wqlo);
    cudaGetSymbolAddress((void**)&wvhi, g_wvhi); cudaGetSymbolAddress((void**)&wvlo, g_wvlo);
    cudaGetSymbolAddress((void**)&wohi, g_wohi); cudaGetSymbolAddress((void**)&wolo, g_wolo);
    cudaGetSymbolAddress((void**)&Qhi, g_Qhi);   cudaGetSymbolAddress((void**)&Qlo, g_Qlo);
    cudaGetSymbolAddress((void**)&Khi, g_Khi);   cudaGetSymbolAddress((void**)&Klo, g_Klo);
    cudaGetSymbolAddress((void**)&Vthi, g_Vthi); cudaGetSymbolAddress((void**)&Vtlo, g_Vtlo);
    cudaGetSymbolAddress((void**)&Chi, g_Chi);   cudaGetSymbolAddress((void**)&Clo, g_Clo);
    cudaGetSymbolAddress((void**)&pmb, g_pm);    cudaGetSymbolAddress((void**)&psb, g_ps);

    const int gemm_smem  = 4 * 128 * 72 * 2;   // 73728
    const int fused_smem = 256 * 4 + (2 * 128 * 136 + 2 * 64 * 136) * 2;

    static bool attr_set = false;
    if (!attr_set) {
        cudaFuncSetAttribute(gemm_bf3, cudaFuncAttributeMaxDynamicSharedMemorySize, gemm_smem);
        cudaFuncSetAttribute(attn_scores_bf, cudaFuncAttributeMaxDynamicSharedMemorySize, gemm_smem);
        cudaFuncSetAttribute(softmax_pv_bf, cudaFuncAttributeMaxDynamicSharedMemorySize, fused_smem);
        attr_set = true;
    }

    // 1) split inputs + weights into bf16 hi/lo planes
    split_kernel<<<(MROWS * DM / 4 + 255) / 256, 256>>>(q, qhi, qlo, MROWS * DM / 4);
    split_kernel<<<(MROWS * DM / 4 + 255) / 256, 256>>>(k, khi, klo, MROWS * DM / 4);
    split_kernel<<<(MROWS * DM / 4 + 255) / 256, 256>>>(v, vhi, vlo, MROWS * DM / 4);
    split_kernel<<<(DM * DM / 4 + 255) / 256, 256>>>(w_q, wqhi, wqlo, DM * DM / 4);
    split_kernel<<<(DM * DM / 4 + 255) / 256, 256>>>(w_v, wvhi, wvlo, DM * DM / 4);
    split_kernel<<<(DM * DM / 4 + 255) / 256, 256>>>(w_o, wohi, wolo, DM * DM / 4);

    // 2) projections
    dim3 gProj(DM / 128, MROWS / 128);   // (8, 32)
    gemm_bf3<<<gProj, 256, gemm_smem>>>(qhi, qlo, wqhi, wqlo, b_q, MROWS, DM, DM, 1, nullptr, Qhi, Qlo);
    gemm_bf3<<<gProj, 256, gemm_smem>>>(khi, klo, wqhi, wqlo, b_q, MROWS, DM, DM, 1, nullptr, Khi, Klo);
    gemm_bf3<<<gProj, 256, gemm_smem>>>(vhi, vlo, wvhi, wvlo, b_v, MROWS, DM, DM, 2, nullptr, Vthi, Vtlo);

    // 3) scores + partial stats
    dim3 gScore(SEQ / 128, SEQ / 128, BATCH * NH);   // (16, 16, 32)
    attn_scores_bf<<<gScore, 256, gemm_smem>>>(Qhi, Qlo, Khi, Klo, mask, attn, pmb, psb);

    // 4) softmax (from partials) + PV
    dim3 gFused(SEQ / 128, BATCH * NH);              // (16, 32)
    softmax_pv_bf<<<gFused, 256, fused_smem>>>(attn, pmb, psb, Vthi, Vtlo, Chi, Clo);

    // 5) output projection -> f32 out
    gemm_bf3<<<gProj, 256, gemm_smem>>>(Chi, Clo, wohi, wolo, b_o, MROWS, DM, DM, 0, out, nullptr, nullptr);
}